// round 6
// baseline (speedup 1.0000x reference)
#include <cuda_runtime.h>
#include <math.h>

#define B_    512
#define EMB_  512
#define CLS_  70722

#define BM 128
#define BN 128
#define BK 16
#define NTHREADS 256

// Scratch (no allocations allowed in kernel_launch)
__device__ float g_ms[B_];
__device__ float g_inv_norm[CLS_];

// ---------------------------------------------------------------------------
// Kernel 1: per-row margin scaler ms[i]  (single block, 512 threads)
// ---------------------------------------------------------------------------
__global__ void margin_kernel(const float* __restrict__ norms,
                              const float* __restrict__ csn) {
    __shared__ float red[B_];
    int t = threadIdx.x;
    float x = fminf(fmaxf(norms[t], 0.001f), 100.0f);
    x = x / (csn[t] + 0.001f);
    x = fminf(fmaxf(x, 0.001f), 100.0f);

    red[t] = x;
    __syncthreads();
    for (int s = B_ / 2; s > 0; s >>= 1) {
        if (t < s) red[t] += red[t + s];
        __syncthreads();
    }
    float mean = red[0] * (1.0f / B_);
    __syncthreads();

    float d = x - mean;
    red[t] = d * d;
    __syncthreads();
    for (int s = B_ / 2; s > 0; s >>= 1) {
        if (t < s) red[t] += red[t + s];
        __syncthreads();
    }
    float stdv = sqrtf(red[0] / (float)(B_ - 1));  // ddof=1

    float msc = (x - mean) / (stdv + 0.001f) * 0.333f;
    g_ms[t] = fminf(fmaxf(msc, -1.0f), 1.0f);
}

// ---------------------------------------------------------------------------
// Kernel 2: inverse column norms of kernel matrix [EMB, CLS] row-major.
// ---------------------------------------------------------------------------
__global__ void colnorm_kernel(const float* __restrict__ Kmat) {
    int j = blockIdx.x * blockDim.x + threadIdx.x;
    if (j >= CLS_) return;
    float s = 0.0f;
#pragma unroll 8
    for (int k = 0; k < EMB_; k++) {
        float v = __ldg(&Kmat[(size_t)k * CLS_ + j]);
        s += v * v;
    }
    g_inv_norm[j] = rsqrtf(s);
}

// ---------------------------------------------------------------------------
// Kernel 3: GEMM + normalize + clip + margin epilogue, fp32 SIMT.
// Tile: 128x128x16, 256 threads, 8x8 per-thread microtile.
// NOTE: CLS_=70722 is 2 mod 4, so Kmat rows are only 8-byte aligned for odd k.
// B-tile global loads therefore use float2 (LDG.64), never float4.
// NOTE: label arrives as int32 (JAX x64-disabled demotes int64 randint).
// ---------------------------------------------------------------------------
__global__ __launch_bounds__(NTHREADS) void gemm_kernel(
    const float* __restrict__ E,
    const float* __restrict__ Kmat,
    const int* __restrict__ label,
    float* __restrict__ out)
{
    __shared__ float As[BK][BM];
    __shared__ float Bs[BK][BN];
    __shared__ float s_inv[BN];
    __shared__ int   s_lab[BM];

    const int tid  = threadIdx.x;
    const int row0 = blockIdx.y * BM;
    const int col0 = blockIdx.x * BN;
    const bool full = (col0 + BN <= CLS_);

    // Prologue: inv norms + labels for this tile
    if (tid < BN) {
        int j = col0 + tid;
        s_inv[tid] = (j < CLS_) ? g_inv_norm[j] : 1.0f;
    }
    if (tid >= 128) {
        s_lab[tid - 128] = label[row0 + (tid - 128)];
    }

    const int tx = tid & 15;   // 16 column groups
    const int ty = tid >> 4;   // 16 row groups

    float4 aReg[2];
    float2 bReg[4];
    float acc[8][8];
#pragma unroll
    for (int m = 0; m < 8; m++)
#pragma unroll
        for (int n = 0; n < 8; n++) acc[m][n] = 0.0f;

    // A tile: 128x16 = 2048 floats = 512 float4; E rows are 16B-aligned (EMB=512).
    auto loadA = [&](int kt, float4* r) {
#pragma unroll
        for (int u = 0; u < 2; u++) {
            int idx = tid + u * 256;          // 0..511
            int ar  = idx >> 2;               // 0..127
            int ac  = (idx & 3) << 2;         // 0,4,8,12
            r[u] = *reinterpret_cast<const float4*>(
                &E[(size_t)(row0 + ar) * EMB_ + kt + ac]);
        }
    };
    // B tile: 16x128 = 2048 floats = 1024 float2; Kmat rows are 8B-aligned.
    auto loadB = [&](int kt, float2* r) {
#pragma unroll
        for (int u = 0; u < 4; u++) {
            int idx = tid + u * 256;          // 0..1023
            int bk  = idx >> 6;               // 0..15
            int bc  = (idx & 63) << 1;        // 0,2,..,126
            const float* p = &Kmat[(size_t)(kt + bk) * CLS_];
            int j = col0 + bc;
            if (full) {
                r[u] = *reinterpret_cast<const float2*>(&p[j]);
            } else {
                float2 v;
                v.x = (j + 0 < CLS_) ? p[j + 0] : 0.0f;
                v.y = (j + 1 < CLS_) ? p[j + 1] : 0.0f;
                r[u] = v;
            }
        }
    };
    auto storeA = [&](float4* r) {
#pragma unroll
        for (int u = 0; u < 2; u++) {
            int idx = tid + u * 256;
            int ar  = idx >> 2;
            int ac  = (idx & 3) << 2;
            As[ac + 0][ar] = r[u].x;
            As[ac + 1][ar] = r[u].y;
            As[ac + 2][ar] = r[u].z;
            As[ac + 3][ar] = r[u].w;
        }
    };
    auto storeB = [&](float2* r) {
#pragma unroll
        for (int u = 0; u < 4; u++) {
            int idx = tid + u * 256;
            int bk  = idx >> 6;
            int bc  = (idx & 63) << 1;
            *reinterpret_cast<float2*>(&Bs[bk][bc]) = r[u];
        }
    };

    loadA(0, aReg); loadB(0, bReg);
    storeA(aReg);   storeB(bReg);
    __syncthreads();

    const int KT = EMB_ / BK;  // 32 k-tiles
    for (int t = 0; t < KT; t++) {
        if (t + 1 < KT) { loadA((t + 1) * BK, aReg); loadB((t + 1) * BK, bReg); }
#pragma unroll
        for (int k = 0; k < BK; k++) {
            float4 a0 = *reinterpret_cast<const float4*>(&As[k][ty * 8]);
            float4 a1 = *reinterpret_cast<const float4*>(&As[k][ty * 8 + 4]);
            float4 b0 = *reinterpret_cast<const float4*>(&Bs[k][tx * 4]);
            float4 b1 = *reinterpret_cast<const float4*>(&Bs[k][tx * 4 + 64]);
            float a[8] = {a0.x, a0.y, a0.z, a0.w, a1.x, a1.y, a1.z, a1.w};
            float b[8] = {b0.x, b0.y, b0.z, b0.w, b1.x, b1.y, b1.z, b1.w};
#pragma unroll
            for (int m = 0; m < 8; m++)
#pragma unroll
                for (int n = 0; n < 8; n++)
                    acc[m][n] = fmaf(a[m], b[n], acc[m][n]);
        }
        __syncthreads();
        if (t + 1 < KT) { storeA(aReg); storeB(bReg); __syncthreads(); }
    }

    // Epilogue: normalize, clip, margin at label, scale by S=64
    const float PI_F = 3.14159265358979323846f;
#pragma unroll
    for (int m = 0; m < 8; m++) {
        int   i   = row0 + ty * 8 + m;
        int   lab = s_lab[ty * 8 + m];
        float ms  = g_ms[i];
        float* orow = &out[(size_t)i * CLS_];
#pragma unroll
        for (int n = 0; n < 8; n++) {
            int cl = (n < 4) ? (tx * 4 + n) : (64 + tx * 4 + (n - 4));
            int j  = col0 + cl;
            if (j < CLS_) {
                float c = acc[m][n] * s_inv[cl];
                c = fminf(fmaxf(c, -0.999f), 0.999f);  // clip to [-1+EPS, 1-EPS]
                float o;
                if (j == lab) {
                    float th = acosf(c) - 0.4f * ms;               // theta - M*ms
                    th = fminf(fmaxf(th, 0.001f), PI_F - 0.001f);  // clip [EPS, pi-EPS]
                    o = (cosf(th) - (0.4f + 0.4f * ms)) * 64.0f;   // (cos - (M+M*ms))*S
                } else {
                    o = c * 64.0f;                                 // cos(arccos(c)) == c
                }
                orow[j] = o;
            }
        }
    }
}

// ---------------------------------------------------------------------------
// Launch: margin scalars -> column norms -> fused GEMM+epilogue
// Inputs (metadata order): embbedings f32[512,512], norms f32[512,1],
// label int32[512] (JAX demotes int64), class_sample_num_ f32[512],
// kernel f32[512,70722]
// ---------------------------------------------------------------------------
extern "C" void kernel_launch(void* const* d_in, const int* in_sizes, int n_in,
                              void* d_out, int out_size) {
    const float* emb   = (const float*)d_in[0];
    const float* norms = (const float*)d_in[1];
    const int*   label = (const int*)d_in[2];
    const float* csn   = (const float*)d_in[3];
    const float* kmat  = (const float*)d_in[4];
    float*       out   = (float*)d_out;

    margin_kernel<<<1, B_>>>(norms, csn);
    colnorm_kernel<<<(CLS_ + 255) / 256, 256>>>(kmat);

    dim3 grid((CLS_ + BN - 1) / BN, B_ / BM);
    gemm_kernel<<<grid, NTHREADS>>>(emb, kmat, label, out);
}

// round 9
// speedup vs baseline: 2.1224x; 2.1224x over previous
#include <cuda_runtime.h>
#include <cuda_bf16.h>
#include <math.h>
#include <stdint.h>

#define B_    512
#define EMB_  512
#define CLS_  70722
#define BK    32
#define NITER 16          // 512 / 32
#define NT    256

// A smem rows padded to 40 bf16 (80 B): conflict-free ldmatrix (stride 80 mod 128
// cycles through all eight 16B chunks over 8 rows).
#define APITCH 80

// dynamic smem offsets (bytes)
#define OFF_A     0        // [var(hi/lo)][buf(0/1)] : 4 x (128*80) = 40960
#define OFF_B     40960    // [var(hi/lo)]           : 2 x (128*80) = 20480
#define OFF_SUMSQ 61440    // 128 f32
#define OFF_INV   61952    // 128 f32
#define OFF_LAB   62464    // 128 i32
#define OFF_MS    62976    // 128 f32
#define SMEM_TOTAL 63488

__device__ float g_ms[B_];
__device__ __align__(16) __nv_bfloat16 g_Ahi[B_ * EMB_];
__device__ __align__(16) __nv_bfloat16 g_Alo[B_ * EMB_];

// ---------------- PTX helpers (all plain-sm_103-legal: sm_80-era) ------------
__device__ __forceinline__ uint32_t smem_u32(const void* p) {
    uint32_t a;
    asm("{ .reg .u64 t; cvta.to.shared.u64 t, %1; cvt.u32.u64 %0, t; }"
        : "=r"(a) : "l"(p));
    return a;
}
__device__ __forceinline__ void cp16(uint32_t dst, const void* src) {
    asm volatile("cp.async.cg.shared.global [%0], [%1], 16;"
                 :: "r"(dst), "l"(src) : "memory");
}
__device__ __forceinline__ void ldm4(uint32_t* r, uint32_t addr) {
    asm volatile("ldmatrix.sync.aligned.m8n8.x4.shared.b16 {%0,%1,%2,%3}, [%4];"
                 : "=r"(r[0]), "=r"(r[1]), "=r"(r[2]), "=r"(r[3]) : "r"(addr));
}
__device__ __forceinline__ void mma16816(float* c, const uint32_t* a,
                                         uint32_t b0, uint32_t b1) {
    asm volatile(
        "mma.sync.aligned.m16n8k16.row.col.f32.bf16.bf16.f32 "
        "{%0,%1,%2,%3}, {%4,%5,%6,%7}, {%8,%9}, {%0,%1,%2,%3};"
        : "+f"(c[0]), "+f"(c[1]), "+f"(c[2]), "+f"(c[3])
        : "r"(a[0]), "r"(a[1]), "r"(a[2]), "r"(a[3]), "r"(b0), "r"(b1));
}

// ---------------------------------------------------------------------------
// Kernel 1: per-row margin scaler ms[i] (single block, 512 threads)
// ---------------------------------------------------------------------------
__global__ void margin_kernel(const float* __restrict__ norms,
                              const float* __restrict__ csn) {
    __shared__ float red[B_];
    int t = threadIdx.x;
    float x = fminf(fmaxf(norms[t], 0.001f), 100.0f);
    x = x / (csn[t] + 0.001f);
    x = fminf(fmaxf(x, 0.001f), 100.0f);

    red[t] = x;
    __syncthreads();
    for (int s = B_ / 2; s > 0; s >>= 1) {
        if (t < s) red[t] += red[t + s];
        __syncthreads();
    }
    float mean = red[0] * (1.0f / B_);
    __syncthreads();
    float d = x - mean;
    red[t] = d * d;
    __syncthreads();
    for (int s = B_ / 2; s > 0; s >>= 1) {
        if (t < s) red[t] += red[t + s];
        __syncthreads();
    }
    float stdv = sqrtf(red[0] / (float)(B_ - 1));
    float msc = (x - mean) / (stdv + 0.001f) * 0.333f;
    g_ms[t] = fminf(fmaxf(msc, -1.0f), 1.0f);
}

// ---------------------------------------------------------------------------
// Kernel 2: split embeddings fp32 -> bf16 hi/lo (row-major [512][512])
// ---------------------------------------------------------------------------
__global__ void prepA_kernel(const float* __restrict__ E) {
    int i = blockIdx.x * blockDim.x + threadIdx.x;
    if (i >= B_ * EMB_) return;
    float x = E[i];
    __nv_bfloat16 h = __float2bfloat16(x);
    float r = x - __bfloat162float(h);
    g_Ahi[i] = h;
    g_Alo[i] = __float2bfloat16(r);
}

// ---------------------------------------------------------------------------
// Kernel 3: mma.sync (HMMA) 3xBF16 GEMM + fused colnorm + margin epilogue.
// Grid (4 mtiles, 553 ntiles), 256 threads = 8 warps (2M x 4N, 64x32 each).
// D += Ah*Bh + Ah*Bl + Al*Bh
// ---------------------------------------------------------------------------
__global__ __launch_bounds__(NT) void gemm_mma(
    const float* __restrict__ Kmat,
    const int* __restrict__ label,
    float* __restrict__ out)
{
    extern __shared__ char smem[];
    const uint32_t sb = smem_u32(smem);
    const int tid  = threadIdx.x;
    const int warp = tid >> 5;
    const int lane = tid & 31;
    const int wm   = warp >> 2;     // 0..1  (64-row slabs)
    const int wn   = warp & 3;      // 0..3  (32-col slabs)
    const int row0 = blockIdx.x * 128;
    const int col0 = blockIdx.y * 128;

    float* s_sumsq = (float*)(smem + OFF_SUMSQ);
    float* s_inv   = (float*)(smem + OFF_INV);
    int*   s_lab   = (int*)(smem + OFF_LAB);
    float* s_ms    = (float*)(smem + OFF_MS);

    if (tid < 128) {
        s_sumsq[tid] = 0.0f;
        s_lab[tid]   = label[row0 + tid];
        s_ms[tid]    = g_ms[row0 + tid];
    }

    // per-lane ldmatrix address components
    const int rA = ((lane >> 3) & 1) * 8 + (lane & 7);  // A tile row within frag
    const int cA = ((lane >> 4) & 1) * 8;               // A k offset (0/8)
    const int rB = (lane & 7) + ((lane >> 4) & 1) * 8;  // B n-row within frag pair
    const int cB = ((lane >> 3) & 1) * 8;               // B k offset (0/8)

    const int nloc = tid & 127;     // conversion: owned column
    const int kh   = tid >> 7;      // conversion: k half (0/1)
    const int gcol = col0 + nloc;
    const bool cok = (gcol < CLS_);

    float acc[4][4][4];
#pragma unroll
    for (int mf = 0; mf < 4; mf++)
#pragma unroll
        for (int nf = 0; nf < 4; nf++)
#pragma unroll
            for (int q = 0; q < 4; q++) acc[mf][nf][q] = 0.0f;

    float breg[16];

    // --- helpers ---
    auto loadBreg = [&](int t) {
        if (cok) {
            const float* base = Kmat + (size_t)(t * BK + kh * 16) * CLS_ + gcol;
#pragma unroll
            for (int i = 0; i < 16; i++) breg[i] = base[(size_t)i * CLS_];
        } else {
#pragma unroll
            for (int i = 0; i < 16; i++) breg[i] = 0.0f;
        }
    };
    auto issueA = [&](int t, int buf) {
        int kt = t * BK;
#pragma unroll
        for (int u = 0; u < 4; u++) {
            int idx = u * 256 + tid;        // 0..1023
            int var = idx >> 9;             // 0=hi 1=lo
            int rs  = idx & 511;
            int m   = rs >> 2;
            int seg = rs & 3;
            const __nv_bfloat16* g =
                (var ? g_Alo : g_Ahi) + (size_t)(row0 + m) * EMB_ + kt + seg * 8;
            cp16(sb + OFF_A + (uint32_t)(var * 2 + buf) * 10240 +
                     (uint32_t)m * APITCH + seg * 16, g);
        }
        asm volatile("cp.async.commit_group;" ::: "memory");
    };
    auto convertB = [&]() {
        float ss = 0.0f;
        uint32_t hi[8], lo[8];
#pragma unroll
        for (int i = 0; i < 8; i++) {
            float x0 = breg[2 * i], x1 = breg[2 * i + 1];
            ss += x0 * x0 + x1 * x1;
            __nv_bfloat16 h0 = __float2bfloat16(x0);
            __nv_bfloat16 h1 = __float2bfloat16(x1);
            float r0 = x0 - __bfloat162float(h0);
            float r1 = x1 - __bfloat162float(h1);
            __nv_bfloat16 l0 = __float2bfloat16(r0);
            __nv_bfloat16 l1 = __float2bfloat16(r1);
            hi[i] = (uint32_t)__bfloat16_as_ushort(h0) |
                    ((uint32_t)__bfloat16_as_ushort(h1) << 16);
            lo[i] = (uint32_t)__bfloat16_as_ushort(l0) |
                    ((uint32_t)__bfloat16_as_ushort(l1) << 16);
        }
        char* bh = smem + OFF_B + nloc * APITCH + kh * 32;
        char* bl = bh + 10240;
        *(uint4*)(bh)      = make_uint4(hi[0], hi[1], hi[2], hi[3]);
        *(uint4*)(bh + 16) = make_uint4(hi[4], hi[5], hi[6], hi[7]);
        *(uint4*)(bl)      = make_uint4(lo[0], lo[1], lo[2], lo[3]);
        *(uint4*)(bl + 16) = make_uint4(lo[4], lo[5], lo[6], lo[7]);
        atomicAdd(&s_sumsq[nloc], ss);
    };
    auto domma = [&](int buf) {
#pragma unroll
        for (int ks = 0; ks < 2; ks++) {
            const int k0 = ks * 16;
            uint32_t bh[8], bl[8], a[16];
            // B frags: ldmatrix.x4 covers two n8 frags per call
#pragma unroll
            for (int nfp = 0; nfp < 2; nfp++) {
                uint32_t addr = sb + OFF_B +
                    (uint32_t)(wn * 32 + nfp * 16 + rB) * APITCH + (k0 + cB) * 2;
                ldm4(&bh[nfp * 4], addr);
                ldm4(&bl[nfp * 4], addr + 10240);
            }
            // A hi frags
#pragma unroll
            for (int mf = 0; mf < 4; mf++) {
                uint32_t addr = sb + OFF_A + (uint32_t)(0 * 2 + buf) * 10240 +
                    (uint32_t)(wm * 64 + mf * 16 + rA) * APITCH + (k0 + cA) * 2;
                ldm4(&a[mf * 4], addr);
            }
            // pass 0: Ah x Bh ; pass 1: Ah x Bl
#pragma unroll
            for (int mf = 0; mf < 4; mf++)
#pragma unroll
                for (int nf = 0; nf < 4; nf++)
                    mma16816(acc[mf][nf], &a[mf * 4], bh[nf * 2], bh[nf * 2 + 1]);
#pragma unroll
            for (int mf = 0; mf < 4; mf++)
#pragma unroll
                for (int nf = 0; nf < 4; nf++)
                    mma16816(acc[mf][nf], &a[mf * 4], bl[nf * 2], bl[nf * 2 + 1]);
            // A lo frags, pass 2: Al x Bh
#pragma unroll
            for (int mf = 0; mf < 4; mf++) {
                uint32_t addr = sb + OFF_A + (uint32_t)(1 * 2 + buf) * 10240 +
                    (uint32_t)(wm * 64 + mf * 16 + rA) * APITCH + (k0 + cA) * 2;
                ldm4(&a[mf * 4], addr);
            }
#pragma unroll
            for (int mf = 0; mf < 4; mf++)
#pragma unroll
                for (int nf = 0; nf < 4; nf++)
                    mma16816(acc[mf][nf], &a[mf * 4], bh[nf * 2], bh[nf * 2 + 1]);
        }
    };

    // --- prologue ---
    issueA(0, 0);
    loadBreg(0);

    // --- mainloop ---
    for (int t = 0; t < NITER; t++) {
        int buf = t & 1;
        asm volatile("cp.async.wait_group 0;" ::: "memory");
        __syncthreads();                 // A(cur) landed; prev MMA readers done
        convertB();                      // breg(t) -> Bs + sumsq
        __syncthreads();                 // Bs visible to all warps
        if (t + 1 < NITER) {
            issueA(t + 1, buf ^ 1);      // DRAM overlaps MMA
            loadBreg(t + 1);             // LDG latency overlaps MMA
        }
        domma(buf);
    }
    __syncthreads();
    if (tid < 128)
        s_inv[tid] = (s_sumsq[tid] > 0.0f) ? rsqrtf(s_sumsq[tid]) : 0.0f;
    __syncthreads();

    // --- epilogue: fragments -> normalize/clip/margin -> float2 stores ---
    const float PI_F = 3.14159265358979323846f;
#pragma unroll
    for (int mf = 0; mf < 4; mf++) {
#pragma unroll
        for (int half = 0; half < 2; half++) {
            int rloc = wm * 64 + mf * 16 + (lane >> 2) + half * 8;
            int lab  = s_lab[rloc];
            float ms = s_ms[rloc];
            float* orow = out + (size_t)(row0 + rloc) * CLS_;
#pragma unroll
            for (int nf = 0; nf < 4; nf++) {
                int cloc = wn * 32 + nf * 8 + 2 * (lane & 3);
                int j = col0 + cloc;
                if (j < CLS_) {          // CLS even, j even -> pair valid
                    float v0 = acc[mf][nf][half * 2 + 0] * s_inv[cloc];
                    float v1 = acc[mf][nf][half * 2 + 1] * s_inv[cloc + 1];
                    v0 = fminf(fmaxf(v0, -0.999f), 0.999f);
                    v1 = fminf(fmaxf(v1, -0.999f), 0.999f);
                    float o0, o1;
                    if (j == lab) {
                        float th = acosf(v0) - 0.4f * ms;
                        th = fminf(fmaxf(th, 0.001f), PI_F - 0.001f);
                        o0 = (cosf(th) - (0.4f + 0.4f * ms)) * 64.0f;
                    } else o0 = v0 * 64.0f;
                    if (j + 1 == lab) {
                        float th = acosf(v1) - 0.4f * ms;
                        th = fminf(fmaxf(th, 0.001f), PI_F - 0.001f);
                        o1 = (cosf(th) - (0.4f + 0.4f * ms)) * 64.0f;
                    } else o1 = v1 * 64.0f;
                    *(float2*)(&orow[j]) = make_float2(o0, o1);
                }
            }
        }
    }
}

// ---------------------------------------------------------------------------
// Launch. Inputs: emb f32[512,512], norms f32[512,1], label i32[512],
// csn f32[512], kernel f32[512,70722]
// ---------------------------------------------------------------------------
extern "C" void kernel_launch(void* const* d_in, const int* in_sizes, int n_in,
                              void* d_out, int out_size) {
    const float* emb   = (const float*)d_in[0];
    const float* norms = (const float*)d_in[1];
    const int*   label = (const int*)d_in[2];
    const float* csn   = (const float*)d_in[3];
    const float* kmat  = (const float*)d_in[4];
    float*       out   = (float*)d_out;

    cudaFuncSetAttribute(gemm_mma, cudaFuncAttributeMaxDynamicSharedMemorySize,
                         SMEM_TOTAL);

    margin_kernel<<<1, B_>>>(norms, csn);
    prepA_kernel<<<(B_ * EMB_ + 255) / 256, 256>>>(emb);

    dim3 grid(4, (CLS_ + 127) / 128);   // mtile fastest -> B tiles L2-shared
    gemm_mma<<<grid, NT, SMEM_TOTAL>>>(kmat, label, out);
}

// round 10
// speedup vs baseline: 2.4985x; 1.1772x over previous
#include <cuda_runtime.h>
#include <cuda_bf16.h>
#include <math.h>
#include <stdint.h>

#define B_    512
#define EMB_  512
#define CLS_  70722
#define BK    32
#define NITER 16          // 512 / 32
#define NT    256

// A/B bf16 smem rows padded to 40 bf16 (80 B): conflict-free ldmatrix
#define APITCH 80

// dynamic smem offsets (bytes)
#define OFF_A     0        // [var(hi/lo)][buf(0/1)] : 4 x (128*80) = 40960
#define OFF_B     40960    // [var(hi/lo)]           : 2 x (128*80) = 20480
#define OFF_STAGE 61440    // fp32 B stage [buf(0/1)][32][128] : 2 x 16384
#define OFF_SUMSQ 94208    // 128 f32
#define OFF_INV   94720    // 128 f32
#define OFF_LAB   95232    // 128 i32
#define OFF_MS    95744    // 128 f32
#define SMEM_TOTAL 96256

__device__ float g_ms[B_];
__device__ __align__(16) __nv_bfloat16 g_Ahi[B_ * EMB_];
__device__ __align__(16) __nv_bfloat16 g_Alo[B_ * EMB_];

// ---------------- PTX helpers (sm_80-era, family-target legal) --------------
__device__ __forceinline__ uint32_t smem_u32(const void* p) {
    uint32_t a;
    asm("{ .reg .u64 t; cvta.to.shared.u64 t, %1; cvt.u32.u64 %0, t; }"
        : "=r"(a) : "l"(p));
    return a;
}
__device__ __forceinline__ void cp16(uint32_t dst, const void* src) {
    asm volatile("cp.async.cg.shared.global [%0], [%1], 16;"
                 :: "r"(dst), "l"(src) : "memory");
}
__device__ __forceinline__ void cp8(uint32_t dst, const void* src) {
    asm volatile("cp.async.ca.shared.global [%0], [%1], 8;"
                 :: "r"(dst), "l"(src) : "memory");
}
__device__ __forceinline__ void ldm4(uint32_t* r, uint32_t addr) {
    asm volatile("ldmatrix.sync.aligned.m8n8.x4.shared.b16 {%0,%1,%2,%3}, [%4];"
                 : "=r"(r[0]), "=r"(r[1]), "=r"(r[2]), "=r"(r[3]) : "r"(addr));
}
__device__ __forceinline__ void mma16816(float* c, const uint32_t* a,
                                         uint32_t b0, uint32_t b1) {
    asm volatile(
        "mma.sync.aligned.m16n8k16.row.col.f32.bf16.bf16.f32 "
        "{%0,%1,%2,%3}, {%4,%5,%6,%7}, {%8,%9}, {%0,%1,%2,%3};"
        : "+f"(c[0]), "+f"(c[1]), "+f"(c[2]), "+f"(c[3])
        : "r"(a[0]), "r"(a[1]), "r"(a[2]), "r"(a[3]), "r"(b0), "r"(b1));
}

// ---------------------------------------------------------------------------
// Kernel 1: per-row margin scaler ms[i] (single block, 512 threads)
// ---------------------------------------------------------------------------
__global__ void margin_kernel(const float* __restrict__ norms,
                              const float* __restrict__ csn) {
    __shared__ float red[B_];
    int t = threadIdx.x;
    float x = fminf(fmaxf(norms[t], 0.001f), 100.0f);
    x = x / (csn[t] + 0.001f);
    x = fminf(fmaxf(x, 0.001f), 100.0f);

    red[t] = x;
    __syncthreads();
    for (int s = B_ / 2; s > 0; s >>= 1) {
        if (t < s) red[t] += red[t + s];
        __syncthreads();
    }
    float mean = red[0] * (1.0f / B_);
    __syncthreads();
    float d = x - mean;
    red[t] = d * d;
    __syncthreads();
    for (int s = B_ / 2; s > 0; s >>= 1) {
        if (t < s) red[t] += red[t + s];
        __syncthreads();
    }
    float stdv = sqrtf(red[0] / (float)(B_ - 1));
    float msc = (x - mean) / (stdv + 0.001f) * 0.333f;
    g_ms[t] = fminf(fmaxf(msc, -1.0f), 1.0f);
}

// ---------------------------------------------------------------------------
// Kernel 2: split embeddings fp32 -> bf16 hi/lo (row-major [512][512])
// ---------------------------------------------------------------------------
__global__ void prepA_kernel(const float* __restrict__ E) {
    int i = blockIdx.x * blockDim.x + threadIdx.x;
    if (i >= B_ * EMB_) return;
    float x = E[i];
    __nv_bfloat16 h = __float2bfloat16(x);
    float r = x - __bfloat162float(h);
    g_Ahi[i] = h;
    g_Alo[i] = __float2bfloat16(r);
}

// ---------------------------------------------------------------------------
// Kernel 3: mma.sync (HMMA) 3xBF16 GEMM + fused colnorm + margin epilogue.
// Grid (4 mtiles, 553 ntiles), 256 threads = 8 warps (2M x 4N, 64x32 each).
// D += Ah*Bh + Ah*Bl + Al*Bh ; 2 CTAs/SM for cross-CTA overlap.
// ---------------------------------------------------------------------------
__global__ __launch_bounds__(NT, 2) void gemm_mma(
    const float* __restrict__ Kmat,
    const int* __restrict__ label,
    float* __restrict__ out)
{
    extern __shared__ char smem[];
    const uint32_t sb = smem_u32(smem);
    const int tid  = threadIdx.x;
    const int warp = tid >> 5;
    const int lane = tid & 31;
    const int wm   = warp >> 2;     // 0..1  (64-row slabs)
    const int wn   = warp & 3;      // 0..3  (32-col slabs)
    const int row0 = blockIdx.x * 128;
    const int col0 = blockIdx.y * 128;

    float* s_sumsq = (float*)(smem + OFF_SUMSQ);
    float* s_inv   = (float*)(smem + OFF_INV);
    int*   s_lab   = (int*)(smem + OFF_LAB);
    float* s_ms    = (float*)(smem + OFF_MS);
    float* stage   = (float*)(smem + OFF_STAGE);

    if (tid < 128) {
        s_sumsq[tid] = 0.0f;
        s_lab[tid]   = label[row0 + tid];
        s_ms[tid]    = g_ms[row0 + tid];
    }

    // per-lane ldmatrix address components
    const int rA = ((lane >> 3) & 1) * 8 + (lane & 7);
    const int cA = ((lane >> 4) & 1) * 8;
    const int rB = (lane & 7) + ((lane >> 4) & 1) * 8;
    const int cB = ((lane >> 3) & 1) * 8;

    const int nloc = tid & 127;     // conversion: owned column
    const int kh   = tid >> 7;      // conversion: k half (0/1)

    float acc[4][4][4];
#pragma unroll
    for (int mf = 0; mf < 4; mf++)
#pragma unroll
        for (int nf = 0; nf < 4; nf++)
#pragma unroll
            for (int q = 0; q < 4; q++) acc[mf][nf][q] = 0.0f;

    // --- helpers ---
    auto issueAB = [&](int t, int buf) {
        int kt = t * BK;
        // A hi/lo: 128 rows x 32 k x bf16 x 2 var = 1024 x 16B chunks
#pragma unroll
        for (int u = 0; u < 4; u++) {
            int idx = u * 256 + tid;
            int var = idx >> 9;
            int rs  = idx & 511;
            int m   = rs >> 2;
            int seg = rs & 3;
            const __nv_bfloat16* g =
                (var ? g_Alo : g_Ahi) + (size_t)(row0 + m) * EMB_ + kt + seg * 8;
            cp16(sb + OFF_A + (uint32_t)(var * 2 + buf) * 10240 +
                     (uint32_t)m * APITCH + seg * 16, g);
        }
        // B fp32 stage: 32 k-rows x 128 cols = 2048 x 8B chunks
        // (Kmat rows only 8B-aligned: CLS*4 % 16 == 8)
#pragma unroll
        for (int u = 0; u < 8; u++) {
            int idx = u * 256 + tid;        // 0..2047
            int k   = idx >> 6;             // 0..31
            int c2  = idx & 63;             // pair index
            int col = col0 + 2 * c2;
            uint32_t dst = sb + OFF_STAGE + (uint32_t)buf * 16384 +
                           (uint32_t)(k * 128 + 2 * c2) * 4;
            if (col < CLS_) {               // CLS even, col even -> pair valid
                cp8(dst, Kmat + (size_t)(kt + k) * CLS_ + col);
            } else {
                *(float2*)(smem + (dst - sb)) = make_float2(0.0f, 0.0f);
            }
        }
        asm volatile("cp.async.commit_group;" ::: "memory");
    };
    auto convertB = [&](int buf) {
        const float* st = stage + buf * 4096 + kh * 16 * 128 + nloc;
        float ss = 0.0f;
        uint32_t hi[8], lo[8];
#pragma unroll
        for (int i = 0; i < 8; i++) {
            float x0 = st[(2 * i) * 128];
            float x1 = st[(2 * i + 1) * 128];
            ss += x0 * x0 + x1 * x1;
            __nv_bfloat16 h0 = __float2bfloat16(x0);
            __nv_bfloat16 h1 = __float2bfloat16(x1);
            float r0 = x0 - __bfloat162float(h0);
            float r1 = x1 - __bfloat162float(h1);
            __nv_bfloat16 l0 = __float2bfloat16(r0);
            __nv_bfloat16 l1 = __float2bfloat16(r1);
            hi[i] = (uint32_t)__bfloat16_as_ushort(h0) |
                    ((uint32_t)__bfloat16_as_ushort(h1) << 16);
            lo[i] = (uint32_t)__bfloat16_as_ushort(l0) |
                    ((uint32_t)__bfloat16_as_ushort(l1) << 16);
        }
        char* bh = smem + OFF_B + nloc * APITCH + kh * 32;
        char* bl = bh + 10240;
        *(uint4*)(bh)      = make_uint4(hi[0], hi[1], hi[2], hi[3]);
        *(uint4*)(bh + 16) = make_uint4(hi[4], hi[5], hi[6], hi[7]);
        *(uint4*)(bl)      = make_uint4(lo[0], lo[1], lo[2], lo[3]);
        *(uint4*)(bl + 16) = make_uint4(lo[4], lo[5], lo[6], lo[7]);
        atomicAdd(&s_sumsq[nloc], ss);
    };
    auto domma = [&](int buf) {
#pragma unroll
        for (int ks = 0; ks < 2; ks++) {
            const int k0 = ks * 16;
            uint32_t bh[8], bl[8], a[16];
#pragma unroll
            for (int nfp = 0; nfp < 2; nfp++) {
                uint32_t addr = sb + OFF_B +
                    (uint32_t)(wn * 32 + nfp * 16 + rB) * APITCH + (k0 + cB) * 2;
                ldm4(&bh[nfp * 4], addr);
                ldm4(&bl[nfp * 4], addr + 10240);
            }
#pragma unroll
            for (int mf = 0; mf < 4; mf++) {
                uint32_t addr = sb + OFF_A + (uint32_t)(0 * 2 + buf) * 10240 +
                    (uint32_t)(wm * 64 + mf * 16 + rA) * APITCH + (k0 + cA) * 2;
                ldm4(&a[mf * 4], addr);
            }
#pragma unroll
            for (int mf = 0; mf < 4; mf++)
#pragma unroll
                for (int nf = 0; nf < 4; nf++)
                    mma16816(acc[mf][nf], &a[mf * 4], bh[nf * 2], bh[nf * 2 + 1]);
#pragma unroll
            for (int mf = 0; mf < 4; mf++)
#pragma unroll
                for (int nf = 0; nf < 4; nf++)
                    mma16816(acc[mf][nf], &a[mf * 4], bl[nf * 2], bl[nf * 2 + 1]);
#pragma unroll
            for (int mf = 0; mf < 4; mf++) {
                uint32_t addr = sb + OFF_A + (uint32_t)(1 * 2 + buf) * 10240 +
                    (uint32_t)(wm * 64 + mf * 16 + rA) * APITCH + (k0 + cA) * 2;
                ldm4(&a[mf * 4], addr);
            }
#pragma unroll
            for (int mf = 0; mf < 4; mf++)
#pragma unroll
                for (int nf = 0; nf < 4; nf++)
                    mma16816(acc[mf][nf], &a[mf * 4], bh[nf * 2], bh[nf * 2 + 1]);
        }
    };

    // --- prologue ---
    issueAB(0, 0);

    // --- mainloop ---
    for (int t = 0; t < NITER; t++) {
        int buf = t & 1;
        asm volatile("cp.async.wait_group 0;" ::: "memory");
        __syncthreads();                 // A/stage(t) landed; domma(t-1) readers done
        convertB(buf);                   // stage[buf] -> Bs bf16 + sumsq
        __syncthreads();                 // Bs visible to all warps
        if (t + 1 < NITER) issueAB(t + 1, buf ^ 1);  // overlaps MMA
        domma(buf);
    }
    __syncthreads();
    if (tid < 128)
        s_inv[tid] = (s_sumsq[tid] > 0.0f) ? rsqrtf(s_sumsq[tid]) : 0.0f;
    __syncthreads();

    // --- epilogue: fragments -> normalize/clip/margin -> float2 stores ---
    const float PI_F = 3.14159265358979323846f;
#pragma unroll
    for (int mf = 0; mf < 4; mf++) {
#pragma unroll
        for (int half = 0; half < 2; half++) {
            int rloc = wm * 64 + mf * 16 + (lane >> 2) + half * 8;
            int lab  = s_lab[rloc];
            float ms = s_ms[rloc];
            float* orow = out + (size_t)(row0 + rloc) * CLS_;
#pragma unroll
            for (int nf = 0; nf < 4; nf++) {
                int cloc = wn * 32 + nf * 8 + 2 * (lane & 3);
                int j = col0 + cloc;
                if (j < CLS_) {          // CLS even, j even -> pair valid
                    float v0 = acc[mf][nf][half * 2 + 0] * s_inv[cloc];
                    float v1 = acc[mf][nf][half * 2 + 1] * s_inv[cloc + 1];
                    v0 = fminf(fmaxf(v0, -0.999f), 0.999f);
                    v1 = fminf(fmaxf(v1, -0.999f), 0.999f);
                    float o0, o1;
                    if (j == lab) {
                        float th = acosf(v0) - 0.4f * ms;
                        th = fminf(fmaxf(th, 0.001f), PI_F - 0.001f);
                        o0 = (cosf(th) - (0.4f + 0.4f * ms)) * 64.0f;
                    } else o0 = v0 * 64.0f;
                    if (j + 1 == lab) {
                        float th = acosf(v1) - 0.4f * ms;
                        th = fminf(fmaxf(th, 0.001f), PI_F - 0.001f);
                        o1 = (cosf(th) - (0.4f + 0.4f * ms)) * 64.0f;
                    } else o1 = v1 * 64.0f;
                    *(float2*)(&orow[j]) = make_float2(o0, o1);
                }
            }
        }
    }
}

// ---------------------------------------------------------------------------
// Launch. Inputs: emb f32[512,512], norms f32[512,1], label i32[512],
// csn f32[512], kernel f32[512,70722]
// ---------------------------------------------------------------------------
extern "C" void kernel_launch(void* const* d_in, const int* in_sizes, int n_in,
                              void* d_out, int out_size) {
    const float* emb   = (const float*)d_in[0];
    const float* norms = (const float*)d_in[1];
    const int*   label = (const int*)d_in[2];
    const float* csn   = (const float*)d_in[3];
    const float* kmat  = (const float*)d_in[4];
    float*       out   = (float*)d_out;

    cudaFuncSetAttribute(gemm_mma, cudaFuncAttributeMaxDynamicSharedMemorySize,
                         SMEM_TOTAL);

    margin_kernel<<<1, B_>>>(norms, csn);
    prepA_kernel<<<(B_ * EMB_ + 255) / 256, 256>>>(emb);

    dim3 grid(4, (CLS_ + 127) / 128);   // mtile fastest -> B tiles L2-shared
    gemm_mma<<<grid, NT, SMEM_TOTAL>>>(kmat, label, out);
}